// round 1
// baseline (speedup 1.0000x reference)
#include <cuda_runtime.h>
#include <math.h>

// Problem constants
#define BB    1024   // batch
#define TT    512    // timesteps
#define ID    64     // input dim
#define HD    256    // hidden dim
#define GD    1024   // 4*H gate dim
#define K0    320    // ID + HD (layer 0 fused K)
#define K1    512    // HD + HD (layer 1 fused K)
#define MB    8      // batch rows per CTA
#define NTHR  256
#define NCTA  (BB / MB)   // 128

// K-major (transposed, concatenated) weights so per-k LDG.128 across the warp is coalesced.
// g_w0t[k][n]: k<64 -> w_ih0[n][k], else w_hh0[n][k-64]
// g_w1t[k][n]: k<256 -> w_ih1[n][k], else w_hh1[n][k-256]
__device__ float g_w0t[K0 * GD];
__device__ float g_w1t[K1 * GD];

__global__ void transpose_weights(const float* __restrict__ w_ih0,
                                  const float* __restrict__ w_hh0,
                                  const float* __restrict__ w_ih1,
                                  const float* __restrict__ w_hh1) {
    int idx = blockIdx.x * blockDim.x + threadIdx.x;
    if (idx < K0 * GD) {
        int k = idx / GD, n = idx % GD;
        g_w0t[idx] = (k < ID) ? w_ih0[n * ID + k] : w_hh0[n * HD + (k - ID)];
    } else {
        int j = idx - K0 * GD;
        if (j < K1 * GD) {
            int k = j / GD, n = j % GD;
            g_w1t[j] = (k < HD) ? w_ih1[n * HD + k] : w_hh1[n * HD + (k - HD)];
        }
    }
}

__device__ __forceinline__ float sigmoidf_(float x) {
    return 1.0f / (1.0f + __expf(-x));
}

// gates[MB][GD] = A[MB][K] @ Wt[K][GD]
// Thread tid owns output columns 4*tid .. 4*tid+3 for all MB rows.
template <int K>
__device__ __forceinline__ void gemm_tile(const float* __restrict__ Wt,
                                          const float* __restrict__ A,   // smem [MB][K]
                                          float* __restrict__ gates,     // smem [MB][GD]
                                          int tid) {
    float acc[MB][4];
#pragma unroll
    for (int r = 0; r < MB; r++) {
        acc[r][0] = 0.f; acc[r][1] = 0.f; acc[r][2] = 0.f; acc[r][3] = 0.f;
    }

#pragma unroll 2
    for (int k = 0; k < K; k += 4) {
        // A fragment: 4 k-values for each of 8 rows (warp-broadcast LDS.128)
        float4 a[MB];
#pragma unroll
        for (int r = 0; r < MB; r++)
            a[r] = *reinterpret_cast<const float4*>(A + r * K + k);

#pragma unroll
        for (int kk = 0; kk < 4; kk++) {
            float4 w = __ldg(reinterpret_cast<const float4*>(Wt + (size_t)(k + kk) * GD) + tid);
#pragma unroll
            for (int r = 0; r < MB; r++) {
                float av = (kk == 0) ? a[r].x : (kk == 1) ? a[r].y : (kk == 2) ? a[r].z : a[r].w;
                acc[r][0] = fmaf(av, w.x, acc[r][0]);
                acc[r][1] = fmaf(av, w.y, acc[r][1]);
                acc[r][2] = fmaf(av, w.z, acc[r][2]);
                acc[r][3] = fmaf(av, w.w, acc[r][3]);
            }
        }
    }

#pragma unroll
    for (int r = 0; r < MB; r++)
        *reinterpret_cast<float4*>(gates + r * GD + 4 * tid) =
            make_float4(acc[r][0], acc[r][1], acc[r][2], acc[r][3]);
}

// Persistent fused 2-layer LSTM + FC. One CTA owns MB=8 batch rows for all of T.
// No inter-CTA dependencies whatsoever.
__global__ void __launch_bounds__(NTHR, 1)
lstm_persistent(const float* __restrict__ x,
                const float* __restrict__ b_ih0, const float* __restrict__ b_hh0,
                const float* __restrict__ b_ih1, const float* __restrict__ b_hh1,
                const float* __restrict__ fc_w,  const float* __restrict__ fc_b,
                float* __restrict__ out) {
    extern __shared__ float sm[];
    float* A0    = sm;                 // [MB][K0]  : [x_t | h0]
    float* A1    = A0 + MB * K0;       // [MB][K1]  : [h0 | h1]
    float* c0    = A1 + MB * K1;       // [MB][HD]
    float* c1    = c0 + MB * HD;       // [MB][HD]
    float* gates = c1 + MB * HD;       // [MB][GD]
    float* bias0 = gates + MB * GD;    // [GD]
    float* bias1 = bias0 + GD;         // [GD]

    const int tid = threadIdx.x;
    const int b0  = blockIdx.x * MB;

    // fold b_ih + b_hh into one bias per layer
    for (int n = tid; n < GD; n += NTHR) {
        bias0[n] = b_ih0[n] + b_hh0[n];
        bias1[n] = b_ih1[n] + b_hh1[n];
    }
    for (int i = tid; i < MB * HD; i += NTHR) { c0[i] = 0.f; c1[i] = 0.f; }
    for (int i = tid; i < MB * K1; i += NTHR) A1[i] = 0.f;
    for (int i = tid; i < MB * K0; i += NTHR) A0[i] = 0.f;
    __syncthreads();

    for (int t = 0; t < TT; t++) {
        // stage x_t into A0[:, 0:ID]
        for (int i = tid; i < MB * ID; i += NTHR) {
            int r = i / ID, col = i % ID;
            A0[r * K0 + col] =
                x[(size_t)(b0 + r) * TT * ID + (size_t)t * ID + col];
        }
        __syncthreads();

        // ---- layer 0: gates = [x_t | h0] @ W0^T ----
        gemm_tile<K0>(g_w0t, A0, gates, tid);
        __syncthreads();

        {   // layer-0 pointwise update; j = tid covers all HD cols
            const int j = tid;
#pragma unroll
            for (int r = 0; r < MB; r++) {
                float gi = gates[r * GD + j]           + bias0[j];
                float gf = gates[r * GD + HD + j]      + bias0[HD + j];
                float gg = gates[r * GD + 2 * HD + j]  + bias0[2 * HD + j];
                float go = gates[r * GD + 3 * HD + j]  + bias0[3 * HD + j];
                float ig = sigmoidf_(gi);
                float fg = sigmoidf_(gf);
                float zg = tanhf(gg);
                float og = sigmoidf_(go);
                float c  = fmaf(fg, c0[r * HD + j], ig * zg);
                c0[r * HD + j] = c;
                float h  = og * tanhf(c);
                A0[r * K0 + ID + j] = h;   // h0 for next step's layer-0 GEMM
                A1[r * K1 + j]      = h;   // h0 input to this step's layer-1 GEMM
            }
        }
        __syncthreads();

        // ---- layer 1: gates = [h0_t | h1] @ W1^T ----
        gemm_tile<K1>(g_w1t, A1, gates, tid);
        __syncthreads();

        {   // layer-1 pointwise update
            const int j = tid;
#pragma unroll
            for (int r = 0; r < MB; r++) {
                float gi = gates[r * GD + j]           + bias1[j];
                float gf = gates[r * GD + HD + j]      + bias1[HD + j];
                float gg = gates[r * GD + 2 * HD + j]  + bias1[2 * HD + j];
                float go = gates[r * GD + 3 * HD + j]  + bias1[3 * HD + j];
                float ig = sigmoidf_(gi);
                float fg = sigmoidf_(gf);
                float zg = tanhf(gg);
                float og = sigmoidf_(go);
                float c  = fmaf(fg, c1[r * HD + j], ig * zg);
                c1[r * HD + j] = c;
                float h  = og * tanhf(c);
                A1[r * K1 + HD + j] = h;   // h1 for next step
            }
        }
        __syncthreads();
    }

    // ---- FC on last h1: out[b] = dot(h1[b], fc_w) + fc_b ----
    const int warp = tid >> 5, lane = tid & 31;
    if (warp < MB) {
        float s = 0.f;
        for (int j = lane; j < HD; j += 32)
            s = fmaf(A1[warp * K1 + HD + j], fc_w[j], s);
#pragma unroll
        for (int o = 16; o; o >>= 1)
            s += __shfl_xor_sync(0xffffffff, s, o);
        if (lane == 0) out[b0 + warp] = s + fc_b[0];
    }
}

extern "C" void kernel_launch(void* const* d_in, const int* in_sizes, int n_in,
                              void* d_out, int out_size) {
    const float* x     = (const float*)d_in[0];
    const float* w_ih0 = (const float*)d_in[1];
    const float* w_hh0 = (const float*)d_in[2];
    const float* b_ih0 = (const float*)d_in[3];
    const float* b_hh0 = (const float*)d_in[4];
    const float* w_ih1 = (const float*)d_in[5];
    const float* w_hh1 = (const float*)d_in[6];
    const float* b_ih1 = (const float*)d_in[7];
    const float* b_hh1 = (const float*)d_in[8];
    const float* fc_w  = (const float*)d_in[9];
    const float* fc_b  = (const float*)d_in[10];
    float* out = (float*)d_out;

    const int smem_bytes =
        (MB * K0 + MB * K1 + 2 * MB * HD + MB * GD + 2 * GD) * (int)sizeof(float);
    cudaFuncSetAttribute(lstm_persistent,
                         cudaFuncAttributeMaxDynamicSharedMemorySize, smem_bytes);

    {
        int total = (K0 + K1) * GD;
        int blocks = (total + 255) / 256;
        transpose_weights<<<blocks, 256>>>(w_ih0, w_hh0, w_ih1, w_hh1);
    }
    lstm_persistent<<<NCTA, NTHR, smem_bytes>>>(
        x, b_ih0, b_hh0, b_ih1, b_hh1, fc_w, fc_b, out);
}

// round 3
// speedup vs baseline: 1.0014x; 1.0014x over previous
#include <cuda_runtime.h>
#include <math.h>

// Problem constants
#define BB    1024   // batch
#define TT    512    // timesteps
#define ID    64     // input dim
#define HD    256    // hidden dim
#define GD    1024   // 4*H gate dim
#define K0    320    // ID + HD (layer 0 fused K)
#define K1    512    // HD + HD (layer 1 fused K)
#define MB    8      // batch rows per CTA
#define NTHR  256
#define NCTA  (BB / MB)   // 128

// K-major (transposed, concatenated) weights so per-k LDG.128 across the warp is coalesced.
// g_w0t[k][n]: k<64 -> w_ih0[n][k], else w_hh0[n][k-64]
// g_w1t[k][n]: k<256 -> w_ih1[n][k], else w_hh1[n][k-256]
__device__ float g_w0t[K0 * GD];
__device__ float g_w1t[K1 * GD];

__global__ void transpose_weights(const float* __restrict__ w_ih0,
                                  const float* __restrict__ w_hh0,
                                  const float* __restrict__ w_ih1,
                                  const float* __restrict__ w_hh1) {
    int idx = blockIdx.x * blockDim.x + threadIdx.x;
    if (idx < K0 * GD) {
        int k = idx / GD, n = idx % GD;
        g_w0t[idx] = (k < ID) ? w_ih0[n * ID + k] : w_hh0[n * HD + (k - ID)];
    } else {
        int j = idx - K0 * GD;
        if (j < K1 * GD) {
            int k = j / GD, n = j % GD;
            g_w1t[j] = (k < HD) ? w_ih1[n * HD + k] : w_hh1[n * HD + (k - HD)];
        }
    }
}

__device__ __forceinline__ float sigmoidf_(float x) {
    return 1.0f / (1.0f + __expf(-x));
}

// gates[MB][GD] = A[MB][K] @ Wt[K][GD]
// Thread tid owns output columns 4*tid .. 4*tid+3 for all MB rows.
template <int K>
__device__ __forceinline__ void gemm_tile(const float* __restrict__ Wt,
                                          const float* __restrict__ A,   // smem [MB][K]
                                          float* __restrict__ gates,     // smem [MB][GD]
                                          int tid) {
    float acc[MB][4];
#pragma unroll
    for (int r = 0; r < MB; r++) {
        acc[r][0] = 0.f; acc[r][1] = 0.f; acc[r][2] = 0.f; acc[r][3] = 0.f;
    }

#pragma unroll 2
    for (int k = 0; k < K; k += 4) {
        // A fragment: 4 k-values for each of 8 rows (warp-broadcast LDS.128)
        float4 a[MB];
#pragma unroll
        for (int r = 0; r < MB; r++)
            a[r] = *reinterpret_cast<const float4*>(A + r * K + k);

#pragma unroll
        for (int kk = 0; kk < 4; kk++) {
            float4 w = __ldg(reinterpret_cast<const float4*>(Wt + (size_t)(k + kk) * GD) + tid);
#pragma unroll
            for (int r = 0; r < MB; r++) {
                float av = (kk == 0) ? a[r].x : (kk == 1) ? a[r].y : (kk == 2) ? a[r].z : a[r].w;
                acc[r][0] = fmaf(av, w.x, acc[r][0]);
                acc[r][1] = fmaf(av, w.y, acc[r][1]);
                acc[r][2] = fmaf(av, w.z, acc[r][2]);
                acc[r][3] = fmaf(av, w.w, acc[r][3]);
            }
        }
    }

#pragma unroll
    for (int r = 0; r < MB; r++)
        *reinterpret_cast<float4*>(gates + r * GD + 4 * tid) =
            make_float4(acc[r][0], acc[r][1], acc[r][2], acc[r][3]);
}

// Persistent fused 2-layer LSTM + FC. One CTA owns MB=8 batch rows for all of T.
// No inter-CTA dependencies whatsoever.
__global__ void __launch_bounds__(NTHR, 1)
lstm_persistent(const float* __restrict__ x,
                const float* __restrict__ b_ih0, const float* __restrict__ b_hh0,
                const float* __restrict__ b_ih1, const float* __restrict__ b_hh1,
                const float* __restrict__ fc_w,  const float* __restrict__ fc_b,
                float* __restrict__ out) {
    extern __shared__ float sm[];
    float* A0    = sm;                 // [MB][K0]  : [x_t | h0]
    float* A1    = A0 + MB * K0;       // [MB][K1]  : [h0 | h1]
    float* c0    = A1 + MB * K1;       // [MB][HD]
    float* c1    = c0 + MB * HD;       // [MB][HD]
    float* gates = c1 + MB * HD;       // [MB][GD]
    float* bias0 = gates + MB * GD;    // [GD]
    float* bias1 = bias0 + GD;         // [GD]

    const int tid = threadIdx.x;
    const int b0  = blockIdx.x * MB;

    // fold b_ih + b_hh into one bias per layer
    for (int n = tid; n < GD; n += NTHR) {
        bias0[n] = b_ih0[n] + b_hh0[n];
        bias1[n] = b_ih1[n] + b_hh1[n];
    }
    for (int i = tid; i < MB * HD; i += NTHR) { c0[i] = 0.f; c1[i] = 0.f; }
    for (int i = tid; i < MB * K1; i += NTHR) A1[i] = 0.f;
    for (int i = tid; i < MB * K0; i += NTHR) A0[i] = 0.f;
    __syncthreads();

    for (int t = 0; t < TT; t++) {
        // stage x_t into A0[:, 0:ID]
        for (int i = tid; i < MB * ID; i += NTHR) {
            int r = i / ID, col = i % ID;
            A0[r * K0 + col] =
                x[(size_t)(b0 + r) * TT * ID + (size_t)t * ID + col];
        }
        __syncthreads();

        // ---- layer 0: gates = [x_t | h0] @ W0^T ----
        gemm_tile<K0>(g_w0t, A0, gates, tid);
        __syncthreads();

        {   // layer-0 pointwise update; j = tid covers all HD cols
            const int j = tid;
#pragma unroll
            for (int r = 0; r < MB; r++) {
                float gi = gates[r * GD + j]           + bias0[j];
                float gf = gates[r * GD + HD + j]      + bias0[HD + j];
                float gg = gates[r * GD + 2 * HD + j]  + bias0[2 * HD + j];
                float go = gates[r * GD + 3 * HD + j]  + bias0[3 * HD + j];
                float ig = sigmoidf_(gi);
                float fg = sigmoidf_(gf);
                float zg = tanhf(gg);
                float og = sigmoidf_(go);
                float c  = fmaf(fg, c0[r * HD + j], ig * zg);
                c0[r * HD + j] = c;
                float h  = og * tanhf(c);
                A0[r * K0 + ID + j] = h;   // h0 for next step's layer-0 GEMM
                A1[r * K1 + j]      = h;   // h0 input to this step's layer-1 GEMM
            }
        }
        __syncthreads();

        // ---- layer 1: gates = [h0_t | h1] @ W1^T ----
        gemm_tile<K1>(g_w1t, A1, gates, tid);
        __syncthreads();

        {   // layer-1 pointwise update
            const int j = tid;
#pragma unroll
            for (int r = 0; r < MB; r++) {
                float gi = gates[r * GD + j]           + bias1[j];
                float gf = gates[r * GD + HD + j]      + bias1[HD + j];
                float gg = gates[r * GD + 2 * HD + j]  + bias1[2 * HD + j];
                float go = gates[r * GD + 3 * HD + j]  + bias1[3 * HD + j];
                float ig = sigmoidf_(gi);
                float fg = sigmoidf_(gf);
                float zg = tanhf(gg);
                float og = sigmoidf_(go);
                float c  = fmaf(fg, c1[r * HD + j], ig * zg);
                c1[r * HD + j] = c;
                float h  = og * tanhf(c);
                A1[r * K1 + HD + j] = h;   // h1 for next step
            }
        }
        __syncthreads();
    }

    // ---- FC on last h1: out[b] = dot(h1[b], fc_w) + fc_b ----
    const int warp = tid >> 5, lane = tid & 31;
    if (warp < MB) {
        float s = 0.f;
        for (int j = lane; j < HD; j += 32)
            s = fmaf(A1[warp * K1 + HD + j], fc_w[j], s);
#pragma unroll
        for (int o = 16; o; o >>= 1)
            s += __shfl_xor_sync(0xffffffff, s, o);
        if (lane == 0) out[b0 + warp] = s + fc_b[0];
    }
}

extern "C" void kernel_launch(void* const* d_in, const int* in_sizes, int n_in,
                              void* d_out, int out_size) {
    const float* x     = (const float*)d_in[0];
    const float* w_ih0 = (const float*)d_in[1];
    const float* w_hh0 = (const float*)d_in[2];
    const float* b_ih0 = (const float*)d_in[3];
    const float* b_hh0 = (const float*)d_in[4];
    const float* w_ih1 = (const float*)d_in[5];
    const float* w_hh1 = (const float*)d_in[6];
    const float* b_ih1 = (const float*)d_in[7];
    const float* b_hh1 = (const float*)d_in[8];
    const float* fc_w  = (const float*)d_in[9];
    const float* fc_b  = (const float*)d_in[10];
    float* out = (float*)d_out;

    const int smem_bytes =
        (MB * K0 + MB * K1 + 2 * MB * HD + MB * GD + 2 * GD) * (int)sizeof(float);
    cudaFuncSetAttribute(lstm_persistent,
                         cudaFuncAttributeMaxDynamicSharedMemorySize, smem_bytes);

    {
        int total = (K0 + K1) * GD;
        int blocks = (total + 255) / 256;
        transpose_weights<<<blocks, 256>>>(w_ih0, w_hh0, w_ih1, w_hh1);
    }
    lstm_persistent<<<NCTA, NTHR, smem_bytes>>>(
        x, b_ih0, b_hh0, b_ih1, b_hh1, fc_w, fc_b, out);
}